// round 3
// baseline (speedup 1.0000x reference)
#include <cuda_runtime.h>

#define BB 2
#define SS 2048
#define DM 4096
#define NH 32
#define HD 128
#define QL 12
#define KL 4
#define NT (BB*SS)   // 4096 tokens

typedef unsigned long long u64;

// ---------------- f32x2 packed-math helpers (sm_103a) ----------------------
__device__ __forceinline__ u64 f2pack(float lo, float hi) {
    u64 r; asm("mov.b64 %0, {%1, %2};" : "=l"(r) : "f"(lo), "f"(hi)); return r;
}
__device__ __forceinline__ void f2unpack(u64 v, float& lo, float& hi) {
    asm("mov.b64 {%0, %1}, %2;" : "=f"(lo), "=f"(hi) : "l"(v));
}
__device__ __forceinline__ u64 f2fma(u64 a, u64 b, u64 c) {
    u64 d; asm("fma.rn.f32x2 %0, %1, %2, %3;" : "=l"(d) : "l"(a), "l"(b), "l"(c)); return d;
}
__device__ __forceinline__ u64 f2mul(u64 a, u64 b) {
    u64 d; asm("mul.rn.f32x2 %0, %1, %2;" : "=l"(d) : "l"(a), "l"(b)); return d;
}
__device__ __forceinline__ u64 f2add(u64 a, u64 b) {
    u64 d; asm("add.rn.f32x2 %0, %1, %2;" : "=l"(d) : "l"(a), "l"(b)); return d;
}
__device__ __forceinline__ float ex2f(float x) {
    float y; asm("ex2.approx.f32 %0, %1;" : "=f"(y) : "f"(x)); return y;
}

// ---------------- scratch ---------------------------------------------------
__device__ __align__(16) float g_Wall[DM*16];       // Wq || Wkv packed [d][16]
__device__ __align__(16) float g_Ckv[NT*KL];
__device__ __align__(16) float g_q  [NT*NH*KL];     // pre-scaled by 0.5*log2e
__device__ __align__(16) float g_A  [NT*NH*KL];
__device__ __align__(16) float g_M  [NH*KL*DM];
__device__ __align__(16) float g_Mb [NH*DM];
__device__ __align__(16) float g_bo [DM];

#define QSCALE 0.7213475204444817f   /* 0.5 * log2(e) */

// ============ Kernel 0: pack Wq||Wkv into [d][16] ===========================
__global__ __launch_bounds__(256) void prepack_kernel(
    const float* __restrict__ Wq, const float* __restrict__ Wkv)
{
    int i = blockIdx.x * 256 + threadIdx.x;   // over DM*16
    int d = i >> 4, c = i & 15;
    g_Wall[i] = (c < QL) ? Wq[(size_t)d*QL + c] : Wkv[(size_t)d*KL + (c - QL)];
}

// ============ Kernel 1: x -> C_q, C_kv, q (reg double-buffered) =============
__global__ __launch_bounds__(512) void proj_kernel(
    const float* __restrict__ x,   const float* __restrict__ bq,
    const float* __restrict__ Wqk, const float* __restrict__ bqk,
    const float* __restrict__ bkv)
{
    __shared__ __align__(16) float xs[32][128];
    __shared__ __align__(16) float ws[16][132];
    __shared__ float cq[32][16];

    const int tid  = threadIdx.x;
    const int tok0 = blockIdx.x * 32;
    const int tok  = tid >> 4;
    const int c    = tid & 15;

    const int i1 = tid + 512;
    const int xt0 = tid >> 5, xq0 = (tid & 31) * 4;
    const int xt1 = i1  >> 5, xq1 = (i1  & 31) * 4;
    const int wd  = tid >> 2, wc  = (tid & 3) * 4;

    float4 xr0, xr1, wr;
    // prefetch chunk 0
    xr0 = *(const float4*)&x[(size_t)(tok0 + xt0)*DM + 0 + xq0];
    xr1 = *(const float4*)&x[(size_t)(tok0 + xt1)*DM + 0 + xq1];
    wr  = *(const float4*)&g_Wall[(size_t)(0 + wd)*16 + wc];

    u64 acc2a = 0ull, acc2b = 0ull;
    for (int c0 = 0; c0 < 32; ++c0) {
        *(float4*)&xs[xt0][xq0] = xr0;
        *(float4*)&xs[xt1][xq1] = xr1;
        ws[wc+0][wd] = wr.x; ws[wc+1][wd] = wr.y;
        ws[wc+2][wd] = wr.z; ws[wc+3][wd] = wr.w;
        __syncthreads();
        if (c0 < 31) {
            int d0 = (c0 + 1) * 128;
            xr0 = *(const float4*)&x[(size_t)(tok0 + xt0)*DM + d0 + xq0];
            xr1 = *(const float4*)&x[(size_t)(tok0 + xt1)*DM + d0 + xq1];
            wr  = *(const float4*)&g_Wall[(size_t)(d0 + wd)*16 + wc];
        }
        const ulonglong2* xp = (const ulonglong2*)&xs[tok][0];
        const ulonglong2* wp = (const ulonglong2*)&ws[c][0];
        #pragma unroll 8
        for (int d = 0; d < 32; d += 2) {
            ulonglong2 xv = xp[d],   wv = wp[d];
            ulonglong2 xw = xp[d+1], ww = wp[d+1];
            acc2a = f2fma(xv.x, wv.x, acc2a);
            acc2b = f2fma(xv.y, wv.y, acc2b);
            acc2a = f2fma(xw.x, ww.x, acc2a);
            acc2b = f2fma(xw.y, ww.y, acc2b);
        }
        __syncthreads();
    }
    float alo, ahi, blo, bhi;
    f2unpack(acc2a, alo, ahi); f2unpack(acc2b, blo, bhi);
    float biased = (alo + ahi) + (blo + bhi) + ((c < QL) ? bq[c] : bkv[c - QL]);
    cq[tok][c] = biased;
    if (c >= QL) g_Ckv[(size_t)(tok0 + tok)*KL + (c - QL)] = biased;
    __syncthreads();

    float cql[QL];
    #pragma unroll
    for (int i = 0; i < QL; ++i) cql[i] = cq[tok][i];
    const int o0 = c * 8;
    #pragma unroll
    for (int oo = 0; oo < 8; ++oo) {
        int o = o0 + oo;
        float s = bqk[o];
        #pragma unroll
        for (int i = 0; i < QL; ++i) s = fmaf(cql[i], Wqk[i*(NH*KL) + o], s);
        g_q[(size_t)(tok0 + tok)*(NH*KL) + o] = QSCALE * s;
    }
}

// ============ Kernel 2: fold Wv_u into Wo (float4-j) ========================
__global__ __launch_bounds__(128) void precM_kernel(
    const float* __restrict__ Wvu, const float* __restrict__ Wo,
    const float* __restrict__ bvu)
{
    __shared__ float vu[KL][HD];
    __shared__ float bvs[HD];
    const int h = blockIdx.y;
    const int j = (blockIdx.x * 128 + threadIdx.x) * 4;
    for (int i = threadIdx.x; i < KL*HD; i += 128) {
        int k = i >> 7, d = i & 127;
        vu[k][d] = Wvu[(size_t)k*(NH*HD) + h*HD + d];
    }
    if (threadIdx.x < HD) bvs[threadIdx.x] = bvu[h*HD + threadIdx.x];
    __syncthreads();

    float4 a0 = {0,0,0,0}, a1 = a0, a2 = a0, a3 = a0, ab = a0;
    #pragma unroll 4
    for (int d = 0; d < HD; ++d) {
        float4 w = *(const float4*)&Wo[(size_t)(h*HD + d)*DM + j];
        float v0 = vu[0][d], v1 = vu[1][d], v2 = vu[2][d], v3 = vu[3][d], vb = bvs[d];
        a0.x=fmaf(v0,w.x,a0.x); a0.y=fmaf(v0,w.y,a0.y); a0.z=fmaf(v0,w.z,a0.z); a0.w=fmaf(v0,w.w,a0.w);
        a1.x=fmaf(v1,w.x,a1.x); a1.y=fmaf(v1,w.y,a1.y); a1.z=fmaf(v1,w.z,a1.z); a1.w=fmaf(v1,w.w,a1.w);
        a2.x=fmaf(v2,w.x,a2.x); a2.y=fmaf(v2,w.y,a2.y); a2.z=fmaf(v2,w.z,a2.z); a2.w=fmaf(v2,w.w,a2.w);
        a3.x=fmaf(v3,w.x,a3.x); a3.y=fmaf(v3,w.y,a3.y); a3.z=fmaf(v3,w.z,a3.z); a3.w=fmaf(v3,w.w,a3.w);
        ab.x=fmaf(vb,w.x,ab.x); ab.y=fmaf(vb,w.y,ab.y); ab.z=fmaf(vb,w.z,ab.z); ab.w=fmaf(vb,w.w,ab.w);
    }
    *(float4*)&g_M[(size_t)(h*KL + 0)*DM + j] = a0;
    *(float4*)&g_M[(size_t)(h*KL + 1)*DM + j] = a1;
    *(float4*)&g_M[(size_t)(h*KL + 2)*DM + j] = a2;
    *(float4*)&g_M[(size_t)(h*KL + 3)*DM + j] = a3;
    *(float4*)&g_Mb[(size_t)h*DM + j] = ab;
}

__global__ __launch_bounds__(256) void biascomb_kernel(const float* __restrict__ bo)
{
    int j = (blockIdx.x * 256 + threadIdx.x) * 4;
    float4 acc = *(const float4*)&bo[j];
    #pragma unroll
    for (int h = 0; h < NH; ++h) {
        float4 m = *(const float4*)&g_Mb[(size_t)h*DM + j];
        acc.x += m.x; acc.y += m.y; acc.z += m.z; acc.w += m.w;
    }
    *(float4*)&g_bo[j] = acc;
}

// ============ Kernel 3: persistent latent attention =========================
// grid 148 x 512 thr. 256 units of (b, h, 512-query tile). Keys SoA in SMEM.
// 4 keys/iter with two independent score chains + accumulator sets.
__global__ __launch_bounds__(512) void attn_kernel()
{
    __shared__ __align__(16) float ckx[SS];
    __shared__ __align__(16) float cky[SS];
    __shared__ __align__(16) float ckz[SS];
    __shared__ __align__(16) float ckw[SS];
    const int tid = threadIdx.x;
    int curb = -1;

    for (int u = blockIdx.x; u < 256; u += 148) {
        const int b = u >> 7, h = (u >> 2) & 31, qt = u & 3;
        if (b != curb) {
            __syncthreads();
            const float4* ckv = (const float4*)(g_Ckv + (size_t)b*SS*KL);
            for (int i = tid; i < SS; i += 512) {
                float4 v = ckv[i];
                ckx[i] = v.x; cky[i] = v.y; ckz[i] = v.z; ckw[i] = v.w;
            }
            __syncthreads();
            curb = b;
        }
        const int tok = b*SS + qt*512 + tid;
        const float4 qv = *(const float4*)(g_q + (size_t)tok*(NH*KL) + h*KL);
        const u64 qx2 = f2pack(qv.x, qv.x);
        const u64 qy2 = f2pack(qv.y, qv.y);
        const u64 qz2 = f2pack(qv.z, qv.z);
        const u64 qw2 = f2pack(qv.w, qv.w);

        const u64* cxp = (const u64*)ckx;
        const u64* cyp = (const u64*)cky;
        const u64* czp = (const u64*)ckz;
        const u64* cwp = (const u64*)ckw;

        u64 lA=0ull, axA=0ull, ayA=0ull, azA=0ull, awA=0ull;
        u64 lB=0ull, axB=0ull, ayB=0ull, azB=0ull, awB=0ull;
        #pragma unroll 4
        for (int k = 0; k < SS/4; ++k) {
            u64 cxa = cxp[2*k],   cya = cyp[2*k],   cza = czp[2*k],   cwa = cwp[2*k];
            u64 cxb = cxp[2*k+1], cyb = cyp[2*k+1], czb = czp[2*k+1], cwb = cwp[2*k+1];
            u64 sa = f2mul(qx2, cxa);
            u64 sb = f2mul(qx2, cxb);
            sa = f2fma(qy2, cya, sa);  sb = f2fma(qy2, cyb, sb);
            sa = f2fma(qz2, cza, sa);  sb = f2fma(qz2, czb, sb);
            sa = f2fma(qw2, cwa, sa);  sb = f2fma(qw2, cwb, sb);
            float s0,s1,s2,s3; f2unpack(sa, s0, s1); f2unpack(sb, s2, s3);
            u64 ea = f2pack(ex2f(s0), ex2f(s1));
            u64 eb = f2pack(ex2f(s2), ex2f(s3));
            lA  = f2add(lA, ea);          lB  = f2add(lB, eb);
            axA = f2fma(ea, cxa, axA);    axB = f2fma(eb, cxb, axB);
            ayA = f2fma(ea, cya, ayA);    ayB = f2fma(eb, cyb, ayB);
            azA = f2fma(ea, cza, azA);    azB = f2fma(eb, czb, azB);
            awA = f2fma(ea, cwa, awA);    awB = f2fma(eb, cwb, awB);
        }
        u64 l2 = f2add(lA, lB);
        u64 ax2 = f2add(axA, axB), ay2 = f2add(ayA, ayB);
        u64 az2 = f2add(azA, azB), aw2 = f2add(awA, awB);
        float l0,l1,x0,x1,y0,y1,z0,z1,w0,w1;
        f2unpack(l2, l0, l1);
        f2unpack(ax2, x0, x1); f2unpack(ay2, y0, y1);
        f2unpack(az2, z0, z1); f2unpack(aw2, w0, w1);
        float inv = 1.f / (l0 + l1);
        float4 r;
        r.x = (x0 + x1) * inv; r.y = (y0 + y1) * inv;
        r.z = (z0 + z1) * inv; r.w = (w0 + w1) * inv;
        *(float4*)(g_A + (size_t)tok*(NH*KL) + h*KL) = r;
    }
}

// ============ Kernel 4: out = A[4096,128] @ M[128,4096] + bo ================
// 128(tok) x 64(j) tile, k-chunk 32, B duplicated in SMEM for direct packed LDS.
__global__ __launch_bounds__(256) void final_kernel(float* __restrict__ out)
{
    __shared__ __align__(16) float Ast[32][130];   // [k][row]
    __shared__ __align__(16) float Bsd[32][128];   // [k][64 j duplicated]
    const int tok0 = blockIdx.y * 128, j0 = blockIdx.x * 64;
    const int tid = threadIdx.x;
    const int tx = tid & 15, ty = tid >> 4;
    const int r0 = ty * 8;

    u64 acc[4][4];
    #pragma unroll
    for (int i = 0; i < 4; ++i)
        #pragma unroll
        for (int j = 0; j < 4; ++j) acc[i][j] = 0ull;

    for (int k0 = 0; k0 < NH*KL; k0 += 32) {
        #pragma unroll
        for (int s = 0; s < 4; ++s) {
            int i = tid + s*256;             // 0..1023
            int r = i >> 3, kq = (i & 7) * 4;
            float4 v = *(const float4*)&g_A[(size_t)(tok0 + r)*(NH*KL) + k0 + kq];
            Ast[kq+0][r] = v.x; Ast[kq+1][r] = v.y;
            Ast[kq+2][r] = v.z; Ast[kq+3][r] = v.w;
        }
        #pragma unroll
        for (int s = 0; s < 2; ++s) {
            int i = tid + s*256;             // 0..511
            int k = i >> 4, jq = (i & 15) * 4;
            float4 v = *(const float4*)&g_M[(size_t)(k0 + k)*DM + j0 + jq];
            float* p = &Bsd[k][jq*2];
            p[0]=v.x; p[1]=v.x; p[2]=v.y; p[3]=v.y;
            p[4]=v.z; p[5]=v.z; p[6]=v.w; p[7]=v.w;
        }
        __syncthreads();
        #pragma unroll 4
        for (int k = 0; k < 32; ++k) {
            ulonglong2 bA = *(const ulonglong2*)&Bsd[k][tx*8];
            ulonglong2 bB = *(const ulonglong2*)&Bsd[k][tx*8 + 4];
            u64 a01 = *(const u64*)&Ast[k][r0 + 0];
            u64 a23 = *(const u64*)&Ast[k][r0 + 2];
            u64 a45 = *(const u64*)&Ast[k][r0 + 4];
            u64 a67 = *(const u64*)&Ast[k][r0 + 6];
            acc[0][0] = f2fma(a01, bA.x, acc[0][0]);
            acc[0][1] = f2fma(a01, bA.y, acc[0][1]);
            acc[0][2] = f2fma(a01, bB.x, acc[0][2]);
            acc[0][3] = f2fma(a01, bB.y, acc[0][3]);
            acc[1][0] = f2fma(a23, bA.x, acc[1][0]);
            acc[1][1] = f2fma(a23, bA.y, acc[1][1]);
            acc[1][2] = f2fma(a23, bB.x, acc[1][2]);
            acc[1][3] = f2fma(a23, bB.y, acc[1][3]);
            acc[2][0] = f2fma(a45, bA.x, acc[2][0]);
            acc[2][1] = f2fma(a45, bA.y, acc[2][1]);
            acc[2][2] = f2fma(a45, bB.x, acc[2][2]);
            acc[2][3] = f2fma(a45, bB.y, acc[2][3]);
            acc[3][0] = f2fma(a67, bA.x, acc[3][0]);
            acc[3][1] = f2fma(a67, bA.y, acc[3][1]);
            acc[3][2] = f2fma(a67, bB.x, acc[3][2]);
            acc[3][3] = f2fma(a67, bB.y, acc[3][3]);
        }
        __syncthreads();
    }

    const float4 bj = *(const float4*)&g_bo[j0 + tx*4];
    #pragma unroll
    for (int i = 0; i < 4; ++i) {
        float lo0, hi0, lo1, hi1, lo2, hi2, lo3, hi3;
        f2unpack(acc[i][0], lo0, hi0);
        f2unpack(acc[i][1], lo1, hi1);
        f2unpack(acc[i][2], lo2, hi2);
        f2unpack(acc[i][3], lo3, hi3);
        float4 ra, rb;
        ra.x = lo0 + bj.x; ra.y = lo1 + bj.y; ra.z = lo2 + bj.z; ra.w = lo3 + bj.w;
        rb.x = hi0 + bj.x; rb.y = hi1 + bj.y; rb.z = hi2 + bj.z; rb.w = hi3 + bj.w;
        size_t row = (size_t)(tok0 + r0 + 2*i);
        *(float4*)&out[row*DM + j0 + tx*4]       = ra;
        *(float4*)&out[(row + 1)*DM + j0 + tx*4] = rb;
    }
}

// ============================================================================
extern "C" void kernel_launch(void* const* d_in, const int* in_sizes, int n_in,
                              void* d_out, int out_size)
{
    const float* x    = (const float*)d_in[0];
    const float* Wq_d = (const float*)d_in[1];
    const float* bq_d = (const float*)d_in[2];
    const float* W_qk = (const float*)d_in[3];
    const float* b_qk = (const float*)d_in[4];
    const float* Wkv_d= (const float*)d_in[5];
    const float* bkv_d= (const float*)d_in[6];
    const float* Wv_u = (const float*)d_in[7];
    const float* bv_u = (const float*)d_in[8];
    const float* Wo   = (const float*)d_in[9];
    const float* bo   = (const float*)d_in[10];
    float* out = (float*)d_out;

    prepack_kernel<<<DM*16/256, 256>>>(Wq_d, Wkv_d);
    proj_kernel<<<NT/32, 512>>>(x, bq_d, W_qk, b_qk, bkv_d);
    precM_kernel<<<dim3(DM/512, NH), 128>>>(Wv_u, Wo, bv_u);
    biascomb_kernel<<<DM/1024, 256>>>(bo);
    attn_kernel<<<148, 512>>>();
    final_kernel<<<dim3(DM/64, NT/128), 256>>>(out);
}

// round 4
// speedup vs baseline: 1.1654x; 1.1654x over previous
#include <cuda_runtime.h>

#define BB 2
#define SS 2048
#define DM 4096
#define NH 32
#define HD 128
#define QL 12
#define KL 4
#define NT (BB*SS)   // 4096 tokens

typedef unsigned long long u64;

// ---------------- f32x2 packed-math helpers (sm_103a) ----------------------
__device__ __forceinline__ u64 f2pack(float lo, float hi) {
    u64 r; asm("mov.b64 %0, {%1, %2};" : "=l"(r) : "f"(lo), "f"(hi)); return r;
}
__device__ __forceinline__ void f2unpack(u64 v, float& lo, float& hi) {
    asm("mov.b64 {%0, %1}, %2;" : "=f"(lo), "=f"(hi) : "l"(v));
}
__device__ __forceinline__ u64 f2fma(u64 a, u64 b, u64 c) {
    u64 d; asm("fma.rn.f32x2 %0, %1, %2, %3;" : "=l"(d) : "l"(a), "l"(b), "l"(c)); return d;
}
__device__ __forceinline__ u64 f2mul(u64 a, u64 b) {
    u64 d; asm("mul.rn.f32x2 %0, %1, %2;" : "=l"(d) : "l"(a), "l"(b)); return d;
}
__device__ __forceinline__ u64 f2add(u64 a, u64 b) {
    u64 d; asm("add.rn.f32x2 %0, %1, %2;" : "=l"(d) : "l"(a), "l"(b)); return d;
}
__device__ __forceinline__ float ex2f(float x) {
    float y; asm("ex2.approx.f32 %0, %1;" : "=f"(y) : "f"(x)); return y;
}

// ---------------- scratch (device globals; no allocations) ----------------
__device__ __align__(16) float g_Ckv[NT*KL];        // 64 KB
__device__ __align__(16) float g_q  [NT*NH*KL];     // 2 MB  (pre-scaled by 0.5*log2e)
__device__ __align__(16) float g_A  [NT*NH*KL];     // 2 MB
__device__ __align__(16) float g_M  [NH*KL*DM];     // 2 MB
__device__ __align__(16) float g_Mb [NH*DM];        // 512 KB

#define QSCALE 0.7213475204444817f   /* 0.5 * log2(e) */

// ============ Kernel 1: x -> C_q, C_kv, q (round-2 known-good) ==============
__global__ __launch_bounds__(512) void proj_kernel(
    const float* __restrict__ x,   const float* __restrict__ Wq,
    const float* __restrict__ bq,  const float* __restrict__ Wqk,
    const float* __restrict__ bqk, const float* __restrict__ Wkv,
    const float* __restrict__ bkv)
{
    __shared__ __align__(16) float xs[32][128];
    __shared__ __align__(16) float ws[16][132];
    __shared__ float cq[32][16];

    const int tid  = threadIdx.x;
    const int tok0 = blockIdx.x * 32;
    const int tok  = tid >> 4;
    const int c    = tid & 15;

    u64 acc2 = 0ull;
    for (int d0 = 0; d0 < DM; d0 += 128) {
        #pragma unroll
        for (int i = tid; i < 32*128; i += 512) {
            int t = i >> 7, d = i & 127;
            xs[t][d] = x[(size_t)(tok0 + t)*DM + d0 + d];
        }
        #pragma unroll
        for (int i = tid; i < 16*128; i += 512) {
            int d = i >> 4, cc = i & 15;
            ws[cc][d] = (cc < QL) ? Wq[(size_t)(d0+d)*QL + cc]
                                  : Wkv[(size_t)(d0+d)*KL + (cc-QL)];
        }
        __syncthreads();
        #pragma unroll 8
        for (int d = 0; d < 128; d += 4) {
            ulonglong2 xv = *(const ulonglong2*)&xs[tok][d];
            ulonglong2 wv = *(const ulonglong2*)&ws[c][d];
            acc2 = f2fma(xv.x, wv.x, acc2);
            acc2 = f2fma(xv.y, wv.y, acc2);
        }
        __syncthreads();
    }
    float alo, ahi; f2unpack(acc2, alo, ahi);
    float biased = (alo + ahi) + ((c < QL) ? bq[c] : bkv[c - QL]);
    cq[tok][c] = biased;
    if (c >= QL) g_Ckv[(size_t)(tok0 + tok)*KL + (c - QL)] = biased;
    __syncthreads();

    float cql[QL];
    #pragma unroll
    for (int i = 0; i < QL; ++i) cql[i] = cq[tok][i];
    const int o0 = c * 8;
    #pragma unroll
    for (int oo = 0; oo < 8; ++oo) {
        int o = o0 + oo;
        float s = bqk[o];
        #pragma unroll
        for (int i = 0; i < QL; ++i) s = fmaf(cql[i], Wqk[i*(NH*KL) + o], s);
        g_q[(size_t)(tok0 + tok)*(NH*KL) + o] = QSCALE * s;
    }
}

// ============ Kernel 2: fold Wv_u into Wo (round-2 known-good) ==============
__global__ __launch_bounds__(256) void precM_kernel(
    const float* __restrict__ Wvu, const float* __restrict__ Wo,
    const float* __restrict__ bvu)
{
    __shared__ float vu[KL][HD];
    __shared__ float bvs[HD];
    const int h = blockIdx.y;
    const int j = blockIdx.x * 256 + threadIdx.x;
    for (int i = threadIdx.x; i < KL*HD; i += 256) {
        int k = i >> 7, d = i & 127;
        vu[k][d] = Wvu[(size_t)k*(NH*HD) + h*HD + d];
    }
    if (threadIdx.x < HD) bvs[threadIdx.x] = bvu[h*HD + threadIdx.x];
    __syncthreads();

    float a0=0.f, a1=0.f, a2=0.f, a3=0.f, ab=0.f;
    #pragma unroll 4
    for (int d = 0; d < HD; ++d) {
        float w = Wo[(size_t)(h*HD + d)*DM + j];
        a0 = fmaf(vu[0][d], w, a0);
        a1 = fmaf(vu[1][d], w, a1);
        a2 = fmaf(vu[2][d], w, a2);
        a3 = fmaf(vu[3][d], w, a3);
        ab = fmaf(bvs[d],   w, ab);
    }
    g_M[(size_t)(h*KL + 0)*DM + j] = a0;
    g_M[(size_t)(h*KL + 1)*DM + j] = a1;
    g_M[(size_t)(h*KL + 2)*DM + j] = a2;
    g_M[(size_t)(h*KL + 3)*DM + j] = a3;
    g_Mb[(size_t)h*DM + j] = ab;
}

// ============ Kernel 3: latent attention, dual-chain ILP ====================
// round-2 grid (8 q-tiles, 32 heads, 2 batch) x 256 thr; 1 thread = 1 query.
// 4 keys/iter, two independent score chains + accumulator sets.
__global__ __launch_bounds__(256) void attn_kernel()
{
    __shared__ __align__(16) float ckx[SS];
    __shared__ __align__(16) float cky[SS];
    __shared__ __align__(16) float ckz[SS];
    __shared__ __align__(16) float ckw[SS];
    const int b = blockIdx.z, h = blockIdx.y;
    const float4* ckv = (const float4*)(g_Ckv + (size_t)b*SS*KL);
    for (int i = threadIdx.x; i < SS; i += 256) {
        float4 v = ckv[i];
        ckx[i] = v.x; cky[i] = v.y; ckz[i] = v.z; ckw[i] = v.w;
    }
    __syncthreads();

    const int tok = b*SS + blockIdx.x*256 + threadIdx.x;
    const float4 qv = *(const float4*)(g_q + (size_t)tok*(NH*KL) + h*KL);
    const u64 qx2 = f2pack(qv.x, qv.x);
    const u64 qy2 = f2pack(qv.y, qv.y);
    const u64 qz2 = f2pack(qv.z, qv.z);
    const u64 qw2 = f2pack(qv.w, qv.w);

    const u64* cxp = (const u64*)ckx;
    const u64* cyp = (const u64*)cky;
    const u64* czp = (const u64*)ckz;
    const u64* cwp = (const u64*)ckw;

    u64 lA=0ull, axA=0ull, ayA=0ull, azA=0ull, awA=0ull;
    u64 lB=0ull, axB=0ull, ayB=0ull, azB=0ull, awB=0ull;
    #pragma unroll 4
    for (int k = 0; k < SS/4; ++k) {
        u64 cxa = cxp[2*k],   cya = cyp[2*k],   cza = czp[2*k],   cwa = cwp[2*k];
        u64 cxb = cxp[2*k+1], cyb = cyp[2*k+1], czb = czp[2*k+1], cwb = cwp[2*k+1];
        u64 sa = f2mul(qx2, cxa);
        u64 sb = f2mul(qx2, cxb);
        sa = f2fma(qy2, cya, sa);  sb = f2fma(qy2, cyb, sb);
        sa = f2fma(qz2, cza, sa);  sb = f2fma(qz2, czb, sb);
        sa = f2fma(qw2, cwa, sa);  sb = f2fma(qw2, cwb, sb);
        float s0,s1,s2,s3; f2unpack(sa, s0, s1); f2unpack(sb, s2, s3);
        u64 ea = f2pack(ex2f(s0), ex2f(s1));
        u64 eb = f2pack(ex2f(s2), ex2f(s3));
        lA  = f2add(lA, ea);          lB  = f2add(lB, eb);
        axA = f2fma(ea, cxa, axA);    axB = f2fma(eb, cxb, axB);
        ayA = f2fma(ea, cya, ayA);    ayB = f2fma(eb, cyb, ayB);
        azA = f2fma(ea, cza, azA);    azB = f2fma(eb, czb, azB);
        awA = f2fma(ea, cwa, awA);    awB = f2fma(eb, cwb, awB);
    }
    u64 l2  = f2add(lA, lB);
    u64 ax2 = f2add(axA, axB), ay2 = f2add(ayA, ayB);
    u64 az2 = f2add(azA, azB), aw2 = f2add(awA, awB);
    float l0,l1,x0,x1,y0,y1,z0,z1,w0,w1;
    f2unpack(l2, l0, l1);
    f2unpack(ax2, x0, x1); f2unpack(ay2, y0, y1);
    f2unpack(az2, z0, z1); f2unpack(aw2, w0, w1);
    float inv = 1.f / (l0 + l1);
    float4 r;
    r.x = (x0 + x1) * inv; r.y = (y0 + y1) * inv;
    r.z = (z0 + z1) * inv; r.w = (w0 + w1) * inv;
    *(float4*)(g_A + (size_t)tok*(NH*KL) + h*KL) = r;
}

// ============ Kernel 4: out = A @ M + (bo + sum_h Mb) (round-2 + fused bias)
__global__ __launch_bounds__(256) void final_kernel(
    float* __restrict__ out, const float* __restrict__ bo)
{
    __shared__ __align__(16) float Ast[64][130];   // [k][row]
    __shared__ __align__(16) float Bs[64][64];     // [k][j]
    const int tok0 = blockIdx.y * 128, j0 = blockIdx.x * 64;
    const int tx = threadIdx.x & 15, ty = threadIdx.x >> 4;
    const int r0 = ty * 8;

    u64 acc[4][4];
    #pragma unroll
    for (int i = 0; i < 4; ++i)
        #pragma unroll
        for (int j = 0; j < 4; ++j) acc[i][j] = 0ull;

    for (int k0 = 0; k0 < NH*KL; k0 += 64) {
        #pragma unroll
        for (int i = threadIdx.x; i < 128*64; i += 256) {
            int r = i >> 6, k = i & 63;
            Ast[k][r] = g_A[(size_t)(tok0 + r)*(NH*KL) + k0 + k];
        }
        #pragma unroll
        for (int i = threadIdx.x; i < 64*64; i += 256) {
            int r = i >> 6, c = i & 63;
            Bs[r][c] = g_M[(size_t)(k0 + r)*DM + j0 + c];
        }
        __syncthreads();
        #pragma unroll 4
        for (int k = 0; k < 64; ++k) {
            float4 bv = *(const float4*)&Bs[k][tx*4];
            u64 b0 = f2pack(bv.x, bv.x);
            u64 b1 = f2pack(bv.y, bv.y);
            u64 b2 = f2pack(bv.z, bv.z);
            u64 b3 = f2pack(bv.w, bv.w);
            u64 a01 = *(const u64*)&Ast[k][r0 + 0];
            u64 a23 = *(const u64*)&Ast[k][r0 + 2];
            u64 a45 = *(const u64*)&Ast[k][r0 + 4];
            u64 a67 = *(const u64*)&Ast[k][r0 + 6];
            acc[0][0] = f2fma(a01, b0, acc[0][0]);
            acc[0][1] = f2fma(a01, b1, acc[0][1]);
            acc[0][2] = f2fma(a01, b2, acc[0][2]);
            acc[0][3] = f2fma(a01, b3, acc[0][3]);
            acc[1][0] = f2fma(a23, b0, acc[1][0]);
            acc[1][1] = f2fma(a23, b1, acc[1][1]);
            acc[1][2] = f2fma(a23, b2, acc[1][2]);
            acc[1][3] = f2fma(a23, b3, acc[1][3]);
            acc[2][0] = f2fma(a45, b0, acc[2][0]);
            acc[2][1] = f2fma(a45, b1, acc[2][1]);
            acc[2][2] = f2fma(a45, b2, acc[2][2]);
            acc[2][3] = f2fma(a45, b3, acc[2][3]);
            acc[3][0] = f2fma(a67, b0, acc[3][0]);
            acc[3][1] = f2fma(a67, b1, acc[3][1]);
            acc[3][2] = f2fma(a67, b2, acc[3][2]);
            acc[3][3] = f2fma(a67, b3, acc[3][3]);
        }
        __syncthreads();
    }

    // effective bias for this thread's 4 columns: bo + sum_h Mb[h]
    float4 bj = *(const float4*)&bo[j0 + tx*4];
    #pragma unroll
    for (int h = 0; h < NH; ++h) {
        float4 m = *(const float4*)&g_Mb[(size_t)h*DM + j0 + tx*4];
        bj.x += m.x; bj.y += m.y; bj.z += m.z; bj.w += m.w;
    }

    #pragma unroll
    for (int i = 0; i < 4; ++i) {
        float lo0, hi0, lo1, hi1, lo2, hi2, lo3, hi3;
        f2unpack(acc[i][0], lo0, hi0);
        f2unpack(acc[i][1], lo1, hi1);
        f2unpack(acc[i][2], lo2, hi2);
        f2unpack(acc[i][3], lo3, hi3);
        float4 ra, rb;
        ra.x = lo0 + bj.x; ra.y = lo1 + bj.y; ra.z = lo2 + bj.z; ra.w = lo3 + bj.w;
        rb.x = hi0 + bj.x; rb.y = hi1 + bj.y; rb.z = hi2 + bj.z; rb.w = hi3 + bj.w;
        size_t row = (size_t)(tok0 + r0 + 2*i);
        *(float4*)&out[row*DM + j0 + tx*4]       = ra;
        *(float4*)&out[(row + 1)*DM + j0 + tx*4] = rb;
    }
}

// ============================================================================
extern "C" void kernel_launch(void* const* d_in, const int* in_sizes, int n_in,
                              void* d_out, int out_size)
{
    const float* x    = (const float*)d_in[0];
    const float* Wq_d = (const float*)d_in[1];
    const float* bq_d = (const float*)d_in[2];
    const float* W_qk = (const float*)d_in[3];
    const float* b_qk = (const float*)d_in[4];
    const float* Wkv_d= (const float*)d_in[5];
    const float* bkv_d= (const float*)d_in[6];
    const float* Wv_u = (const float*)d_in[7];
    const float* bv_u = (const float*)d_in[8];
    const float* Wo   = (const float*)d_in[9];
    const float* bo   = (const float*)d_in[10];
    float* out = (float*)d_out;

    proj_kernel<<<NT/32, 512>>>(x, Wq_d, bq_d, W_qk, b_qk, Wkv_d, bkv_d);
    precM_kernel<<<dim3(DM/256, NH), 256>>>(Wv_u, Wo, bv_u);
    attn_kernel<<<dim3(SS/256, NH, BB), 256>>>();
    final_kernel<<<dim3(DM/64, NT/128), 256>>>(out, bo);
}

// round 5
// speedup vs baseline: 1.2768x; 1.0957x over previous
#include <cuda_runtime.h>

#define BB 2
#define SS 2048
#define DM 4096
#define NH 32
#define HD 128
#define QL 12
#define KL 4
#define NT (BB*SS)   // 4096 tokens

typedef unsigned long long u64;

// ---------------- f32x2 packed-math helpers (sm_103a) ----------------------
__device__ __forceinline__ u64 f2pack(float lo, float hi) {
    u64 r; asm("mov.b64 %0, {%1, %2};" : "=l"(r) : "f"(lo), "f"(hi)); return r;
}
__device__ __forceinline__ void f2unpack(u64 v, float& lo, float& hi) {
    asm("mov.b64 {%0, %1}, %2;" : "=f"(lo), "=f"(hi) : "l"(v));
}
__device__ __forceinline__ u64 f2fma(u64 a, u64 b, u64 c) {
    u64 d; asm("fma.rn.f32x2 %0, %1, %2, %3;" : "=l"(d) : "l"(a), "l"(b), "l"(c)); return d;
}
__device__ __forceinline__ u64 f2mul(u64 a, u64 b) {
    u64 d; asm("mul.rn.f32x2 %0, %1, %2;" : "=l"(d) : "l"(a), "l"(b)); return d;
}
__device__ __forceinline__ u64 f2add(u64 a, u64 b) {
    u64 d; asm("add.rn.f32x2 %0, %1, %2;" : "=l"(d) : "l"(a), "l"(b)); return d;
}
__device__ __forceinline__ float ex2f(float x) {
    float y; asm("ex2.approx.f32 %0, %1;" : "=f"(y) : "f"(x)); return y;
}

// ---------------- scratch (device globals; no allocations) ----------------
__device__ __align__(16) float g_Ckv[NT*KL];        // 64 KB
__device__ __align__(16) float g_q  [NT*NH*KL];     // 2 MB  (pre-scaled by 0.5*log2e)
__device__ __align__(16) float g_A  [NT*NH*KL];     // 2 MB
__device__ __align__(16) float g_M  [NH*KL*DM];     // 2 MB
__device__ __align__(16) float g_Mb [NH*DM];        // 512 KB

#define QSCALE 0.7213475204444817f   /* 0.5 * log2(e) */

// ============ Kernel 1: x -> C_q, C_kv, q (round-2 known-good) ==============
__global__ __launch_bounds__(512) void proj_kernel(
    const float* __restrict__ x,   const float* __restrict__ Wq,
    const float* __restrict__ bq,  const float* __restrict__ Wqk,
    const float* __restrict__ bqk, const float* __restrict__ Wkv,
    const float* __restrict__ bkv)
{
    __shared__ __align__(16) float xs[32][128];
    __shared__ __align__(16) float ws[16][132];
    __shared__ float cq[32][16];

    const int tid  = threadIdx.x;
    const int tok0 = blockIdx.x * 32;
    const int tok  = tid >> 4;
    const int c    = tid & 15;

    u64 acc2 = 0ull;
    for (int d0 = 0; d0 < DM; d0 += 128) {
        #pragma unroll
        for (int i = tid; i < 32*128; i += 512) {
            int t = i >> 7, d = i & 127;
            xs[t][d] = x[(size_t)(tok0 + t)*DM + d0 + d];
        }
        #pragma unroll
        for (int i = tid; i < 16*128; i += 512) {
            int d = i >> 4, cc = i & 15;
            ws[cc][d] = (cc < QL) ? Wq[(size_t)(d0+d)*QL + cc]
                                  : Wkv[(size_t)(d0+d)*KL + (cc-QL)];
        }
        __syncthreads();
        #pragma unroll 8
        for (int d = 0; d < 128; d += 4) {
            ulonglong2 xv = *(const ulonglong2*)&xs[tok][d];
            ulonglong2 wv = *(const ulonglong2*)&ws[c][d];
            acc2 = f2fma(xv.x, wv.x, acc2);
            acc2 = f2fma(xv.y, wv.y, acc2);
        }
        __syncthreads();
    }
    float alo, ahi; f2unpack(acc2, alo, ahi);
    float biased = (alo + ahi) + ((c < QL) ? bq[c] : bkv[c - QL]);
    cq[tok][c] = biased;
    if (c >= QL) g_Ckv[(size_t)(tok0 + tok)*KL + (c - QL)] = biased;
    __syncthreads();

    float cql[QL];
    #pragma unroll
    for (int i = 0; i < QL; ++i) cql[i] = cq[tok][i];
    const int o0 = c * 8;
    #pragma unroll
    for (int oo = 0; oo < 8; ++oo) {
        int o = o0 + oo;
        float s = bqk[o];
        #pragma unroll
        for (int i = 0; i < QL; ++i) s = fmaf(cql[i], Wqk[i*(NH*KL) + o], s);
        g_q[(size_t)(tok0 + tok)*(NH*KL) + o] = QSCALE * s;
    }
}

// ============ Kernel 2: fold Wv_u into Wo (round-2 known-good) ==============
__global__ __launch_bounds__(256) void precM_kernel(
    const float* __restrict__ Wvu, const float* __restrict__ Wo,
    const float* __restrict__ bvu)
{
    __shared__ float vu[KL][HD];
    __shared__ float bvs[HD];
    const int h = blockIdx.y;
    const int j = blockIdx.x * 256 + threadIdx.x;
    for (int i = threadIdx.x; i < KL*HD; i += 256) {
        int k = i >> 7, d = i & 127;
        vu[k][d] = Wvu[(size_t)k*(NH*HD) + h*HD + d];
    }
    if (threadIdx.x < HD) bvs[threadIdx.x] = bvu[h*HD + threadIdx.x];
    __syncthreads();

    float a0=0.f, a1=0.f, a2=0.f, a3=0.f, ab=0.f;
    #pragma unroll 4
    for (int d = 0; d < HD; ++d) {
        float w = Wo[(size_t)(h*HD + d)*DM + j];
        a0 = fmaf(vu[0][d], w, a0);
        a1 = fmaf(vu[1][d], w, a1);
        a2 = fmaf(vu[2][d], w, a2);
        a3 = fmaf(vu[3][d], w, a3);
        ab = fmaf(bvs[d],   w, ab);
    }
    g_M[(size_t)(h*KL + 0)*DM + j] = a0;
    g_M[(size_t)(h*KL + 1)*DM + j] = a1;
    g_M[(size_t)(h*KL + 2)*DM + j] = a2;
    g_M[(size_t)(h*KL + 3)*DM + j] = a3;
    g_Mb[(size_t)h*DM + j] = ab;
}

// ============ Kernel 3: latent attention — 128-thr CTAs, 1-wave grid ========
// grid (16 q-tiles, 32 heads, 2 batch) = 1024 CTAs; ~7 resident/SM (32KB smem)
// 4 keys/iter, two independent score chains + accumulator sets, LDS.128 keys.
__global__ __launch_bounds__(128) void attn_kernel()
{
    __shared__ __align__(16) float ckx[SS];
    __shared__ __align__(16) float cky[SS];
    __shared__ __align__(16) float ckz[SS];
    __shared__ __align__(16) float ckw[SS];
    const int b = blockIdx.z, h = blockIdx.y;
    const float4* ckv = (const float4*)(g_Ckv + (size_t)b*SS*KL);
    for (int i = threadIdx.x; i < SS; i += 128) {
        float4 v = ckv[i];
        ckx[i] = v.x; cky[i] = v.y; ckz[i] = v.z; ckw[i] = v.w;
    }
    __syncthreads();

    const int tok = b*SS + blockIdx.x*128 + threadIdx.x;
    const float4 qv = *(const float4*)(g_q + (size_t)tok*(NH*KL) + h*KL);
    const u64 qx2 = f2pack(qv.x, qv.x);
    const u64 qy2 = f2pack(qv.y, qv.y);
    const u64 qz2 = f2pack(qv.z, qv.z);
    const u64 qw2 = f2pack(qv.w, qv.w);

    const ulonglong2* cxp = (const ulonglong2*)ckx;
    const ulonglong2* cyp = (const ulonglong2*)cky;
    const ulonglong2* czp = (const ulonglong2*)ckz;
    const ulonglong2* cwp = (const ulonglong2*)ckw;

    u64 lA=0ull, axA=0ull, ayA=0ull, azA=0ull, awA=0ull;
    u64 lB=0ull, axB=0ull, ayB=0ull, azB=0ull, awB=0ull;
    #pragma unroll 4
    for (int k = 0; k < SS/4; ++k) {
        ulonglong2 cx2 = cxp[k], cy2 = cyp[k], cz2 = czp[k], cw2 = cwp[k];
        u64 sa = f2mul(qx2, cx2.x);
        u64 sb = f2mul(qx2, cx2.y);
        sa = f2fma(qy2, cy2.x, sa);  sb = f2fma(qy2, cy2.y, sb);
        sa = f2fma(qz2, cz2.x, sa);  sb = f2fma(qz2, cz2.y, sb);
        sa = f2fma(qw2, cw2.x, sa);  sb = f2fma(qw2, cw2.y, sb);
        float s0,s1,s2,s3; f2unpack(sa, s0, s1); f2unpack(sb, s2, s3);
        u64 ea = f2pack(ex2f(s0), ex2f(s1));
        u64 eb = f2pack(ex2f(s2), ex2f(s3));
        lA  = f2add(lA, ea);             lB  = f2add(lB, eb);
        axA = f2fma(ea, cx2.x, axA);     axB = f2fma(eb, cx2.y, axB);
        ayA = f2fma(ea, cy2.x, ayA);     ayB = f2fma(eb, cy2.y, ayB);
        azA = f2fma(ea, cz2.x, azA);     azB = f2fma(eb, cz2.y, azB);
        awA = f2fma(ea, cw2.x, awA);     awB = f2fma(eb, cw2.y, awB);
    }
    u64 l2  = f2add(lA, lB);
    u64 ax2 = f2add(axA, axB), ay2 = f2add(ayA, ayB);
    u64 az2 = f2add(azA, azB), aw2 = f2add(awA, awB);
    float l0,l1,x0,x1,y0,y1,z0,z1,w0,w1;
    f2unpack(l2, l0, l1);
    f2unpack(ax2, x0, x1); f2unpack(ay2, y0, y1);
    f2unpack(az2, z0, z1); f2unpack(aw2, w0, w1);
    float inv = 1.f / (l0 + l1);
    float4 r;
    r.x = (x0 + x1) * inv; r.y = (y0 + y1) * inv;
    r.z = (z0 + z1) * inv; r.w = (w0 + w1) * inv;
    *(float4*)(g_A + (size_t)tok*(NH*KL) + h*KL) = r;
}

// ============ Kernel 4: out = A @ M + (bo + sum_h Mb) =======================
// 256(tok) x 64(j) tile, 256 thr, 16x4 microtile (rows strided 32 -> LDS.64
// row-pairs, conflict-free with stride 258). k-chunks of 32.
__global__ __launch_bounds__(256) void final_kernel(
    float* __restrict__ out, const float* __restrict__ bo)
{
    __shared__ __align__(16) float Ast[32][258];   // [k][row], stride 258
    __shared__ __align__(16) float Bs[32][68];     // [k][j], stride 68 (16B-aligned rows)
    const int tok0 = blockIdx.y * 256, j0 = blockIdx.x * 64;
    const int tid = threadIdx.x;
    const int tx = tid & 15, ty = tid >> 4;

    u64 acc[8][4];
    #pragma unroll
    for (int i = 0; i < 8; ++i)
        #pragma unroll
        for (int j = 0; j < 4; ++j) acc[i][j] = 0ull;

    for (int k0 = 0; k0 < NH*KL; k0 += 32) {
        // A: 256 rows x 32 k, transposed into Ast[k][r]
        #pragma unroll
        for (int s = 0; s < 8; ++s) {
            int i = tid + s*256;          // 0..2047
            int r = i >> 3, kq = (i & 7) * 4;
            float4 v = *(const float4*)&g_A[(size_t)(tok0 + r)*(NH*KL) + k0 + kq];
            Ast[kq+0][r] = v.x; Ast[kq+1][r] = v.y;
            Ast[kq+2][r] = v.z; Ast[kq+3][r] = v.w;
        }
        // B: 32 k x 64 j
        #pragma unroll
        for (int s = 0; s < 2; ++s) {
            int i = tid + s*256;          // 0..511
            int k = i >> 4, jq = (i & 15) * 4;
            *(float4*)&Bs[k][jq] = *(const float4*)&g_M[(size_t)(k0 + k)*DM + j0 + jq];
        }
        __syncthreads();
        #pragma unroll 2
        for (int k = 0; k < 32; ++k) {
            float4 bv = *(const float4*)&Bs[k][tx*4];
            u64 b0 = f2pack(bv.x, bv.x);
            u64 b1 = f2pack(bv.y, bv.y);
            u64 b2 = f2pack(bv.z, bv.z);
            u64 b3 = f2pack(bv.w, bv.w);
            #pragma unroll
            for (int i = 0; i < 8; ++i) {
                u64 a = *(const u64*)&Ast[k][ty*2 + 32*i];
                acc[i][0] = f2fma(a, b0, acc[i][0]);
                acc[i][1] = f2fma(a, b1, acc[i][1]);
                acc[i][2] = f2fma(a, b2, acc[i][2]);
                acc[i][3] = f2fma(a, b3, acc[i][3]);
            }
        }
        __syncthreads();
    }

    // effective bias for this thread's 4 columns: bo + sum_h Mb[h]
    float4 bj = *(const float4*)&bo[j0 + tx*4];
    #pragma unroll
    for (int h = 0; h < NH; ++h) {
        float4 m = *(const float4*)&g_Mb[(size_t)h*DM + j0 + tx*4];
        bj.x += m.x; bj.y += m.y; bj.z += m.z; bj.w += m.w;
    }

    #pragma unroll
    for (int i = 0; i < 8; ++i) {
        float lo0, hi0, lo1, hi1, lo2, hi2, lo3, hi3;
        f2unpack(acc[i][0], lo0, hi0);
        f2unpack(acc[i][1], lo1, hi1);
        f2unpack(acc[i][2], lo2, hi2);
        f2unpack(acc[i][3], lo3, hi3);
        float4 ra, rb;
        ra.x = lo0 + bj.x; ra.y = lo1 + bj.y; ra.z = lo2 + bj.z; ra.w = lo3 + bj.w;
        rb.x = hi0 + bj.x; rb.y = hi1 + bj.y; rb.z = hi2 + bj.z; rb.w = hi3 + bj.w;
        size_t row = (size_t)(tok0 + ty*2 + 32*i);
        *(float4*)&out[row*DM + j0 + tx*4]       = ra;
        *(float4*)&out[(row + 1)*DM + j0 + tx*4] = rb;
    }
}

// ============================================================================
extern "C" void kernel_launch(void* const* d_in, const int* in_sizes, int n_in,
                              void* d_out, int out_size)
{
    const float* x    = (const float*)d_in[0];
    const float* Wq_d = (const float*)d_in[1];
    const float* bq_d = (const float*)d_in[2];
    const float* W_qk = (const float*)d_in[3];
    const float* b_qk = (const float*)d_in[4];
    const float* Wkv_d= (const float*)d_in[5];
    const float* bkv_d= (const float*)d_in[6];
    const float* Wv_u = (const float*)d_in[7];
    const float* bv_u = (const float*)d_in[8];
    const float* Wo   = (const float*)d_in[9];
    const float* bo   = (const float*)d_in[10];
    float* out = (float*)d_out;

    proj_kernel<<<NT/32, 512>>>(x, Wq_d, bq_d, W_qk, b_qk, Wkv_d, bkv_d);
    precM_kernel<<<dim3(DM/256, NH), 256>>>(Wv_u, Wo, bv_u);
    attn_kernel<<<dim3(SS/128, NH, BB), 128>>>();
    final_kernel<<<dim3(DM/64, NT/256), 256>>>(out, bo);
}